// round 14
// baseline (speedup 1.0000x reference)
#include <cuda_runtime.h>
#include <cuda_fp16.h>
#include <cstdint>

// Problem constants
#define BB     32
#define DD     64
#define HWSZ   4096
#define NPIX   131072
#define KK     1024
#define ZSIZE  8388608
#define ENC_OFF (1 + ZSIZE + 1)     // vq_loss(1), z_q, perplexity(1), encodings

#define M_TILE  128                 // pixels per CTA (256 threads, 16 px/warp)
#define PITCH   68                  // z row pitch in words
#define PITCH_B 36                  // B row pitch in words (32 half2 words + 4 pad)

// Shared memory word offsets
#define ZS_W   0                    // z rows: 128 x PITCH            (8704)
#define B0_W   8704                 // B buf0: 128 codes x PITCH_B    (4608)
#define B1_W   13312                // B buf1                         (4608)
#define E2_W   17920                // e2s[1024]
#define X2_W   18944                // x2s[128]
#define BK_W   19072                // bks[128]
#define WS_W   19200                // warp partials[8]
#define SMEM_WORDS 19208
#define SMEM_BYTES (SMEM_WORDS * 4) // 76832 B -> 2 CTAs/SM

// Scratch (device globals; no allocation allowed)
__device__ int    g_counts[KK];
__device__ double g_loss;
__device__ float  g_e2[KK];
// fp16(1024*e) packed half2 words, 32 per code (128B rows), word-PERMUTED so
// one uint4 load yields two k-steps of one B fragment column:
// old word j (j = 8*ks + 4*h + kq) lives at pos = kq*8 + ks*2 + h.
__device__ __align__(16) uint32_t g_embpack[KK][32];

// ---------------------------------------------------------------------------
// Helpers
// ---------------------------------------------------------------------------
__device__ __forceinline__ uint32_t smem_u32(const void* p) {
    uint32_t a;
    asm("{ .reg .u64 t; cvta.to.shared.u64 t, %1; cvt.u32.u64 %0, t; }" : "=r"(a) : "l"(p));
    return a;
}
__device__ __forceinline__ uint32_t pack_h2(float a, float b) {
    __half2 h = __halves2half2(__float2half_rn(a), __float2half_rn(b));
    return *(uint32_t*)&h;
}
__device__ __forceinline__ void mma_f16(float c[4], const uint32_t a[4],
                                        uint32_t b0, uint32_t b1) {
    asm volatile("mma.sync.aligned.m16n8k16.row.col.f32.f16.f16.f32 "
                 "{%0,%1,%2,%3}, {%4,%5,%6,%7}, {%8,%9}, {%0,%1,%2,%3};"
                 : "+f"(c[0]), "+f"(c[1]), "+f"(c[2]), "+f"(c[3])
                 : "r"(a[0]), "r"(a[1]), "r"(a[2]), "r"(a[3]), "r"(b0), "r"(b1));
}
__device__ __forceinline__ void cp16(uint32_t dst, const void* src) {
    asm volatile("cp.async.cg.shared.global [%0], [%1], 16;" :: "r"(dst), "l"(src));
}
#define CP_COMMIT() asm volatile("cp.async.commit_group;" ::: "memory")
#define CP_WAIT0()  asm volatile("cp.async.wait_group 0;" ::: "memory")

// Branchless MAX-top2 update (strict >: earlier/lower index kept on ties).
// (Byte-identical behavior to the twice-validated R11 tracker.)
#define TOP2MAX(m, k, m1, i1, m2, i2) do {                 \
    bool g1 = (m) > (m1);                                  \
    bool g2 = (m) > (m2);                                  \
    float _nm2 = g1 ? (m1) : (g2 ? (m) : (m2));            \
    int   _ni2 = g1 ? (i1) : (g2 ? (k) : (i2));            \
    (m1) = g1 ? (m) : (m1);                                \
    (i1) = g1 ? (k) : (i1);                                \
    (m2) = _nm2; (i2) = _ni2;                              \
} while (0)

// Exact fp32 distance, replicating round-5's verified formula/order exactly.
__device__ __forceinline__ float exact_dist(const float* zrow, float x2, int k,
                                            const float* __restrict__ emb,
                                            const float* e2s) {
    const float4* e4 = (const float4*)(emb + k * 64);
    const float4* z4 = (const float4*)zrow;
    float s0 = 0.f, s1 = 0.f, s2 = 0.f, s3 = 0.f;
    #pragma unroll
    for (int i = 0; i < 16; i++) {
        float4 e = e4[i], zv = z4[i];
        s0 += zv.x * e.x; s1 += zv.y * e.y; s2 += zv.z * e.z; s3 += zv.w * e.w;
    }
    float ip = (s0 + s1) + (s2 + s3);
    return (x2 + e2s[k]) - 2.0f * ip;
}

// Stage one 128-code round: 128 rows x 128B at pitch 144B.
__device__ __forceinline__ void stage_B(uint32_t sb, int bufw, int round, int tid) {
    const char* src = (const char*)&g_embpack[round * 128][0];
    #pragma unroll
    for (int t = 0; t < 4; t++) {
        int idx = tid + t * 256;
        int row = idx >> 3, j = idx & 7;            // 8 x 16B = 128B per row
        uint32_t dst = sb + (uint32_t)(bufw + row * PITCH_B) * 4 + j * 16;
        cp16(dst, src + row * 128 + j * 16);
    }
}

// ---------------------------------------------------------------------------
// Prep: one code per warp. e2 (warp-reduced), fp16(1024*e) packed with the
// uint4-friendly word permutation, zero scratch. Grid 128 x 256.
// ---------------------------------------------------------------------------
__global__ void prep_kernel(const float* __restrict__ emb) {
    const int code = blockIdx.x * 8 + (threadIdx.x >> 5);
    const int lane = threadIdx.x & 31;
    float2 v = ((const float2*)(emb + code * 64))[lane];

    float sq = v.x * v.x + v.y * v.y;
    #pragma unroll
    for (int off = 16; off; off >>= 1) sq += __shfl_xor_sync(0xffffffffu, sq, off);
    if (lane == 0) g_e2[code] = sq;

    // lane = 8*ks + 4*h + kq  ->  pos = kq*8 + ks*2 + h
    int ks = lane >> 3, h = (lane >> 2) & 1, kqf = lane & 3;
    g_embpack[code][kqf * 8 + ks * 2 + h] = pack_h2(v.x * 1024.0f, v.y * 1024.0f);

    int gid = blockIdx.x * 256 + threadIdx.x;
    if (gid < KK) g_counts[gid] = 0;
    if (gid == 0) g_loss = 0.0;
}

// ---------------------------------------------------------------------------
// Main fused kernel: hi-only fp16 mma ranking (R11's validated fp32 top-2
// trackers) + quad-merge + exact fp32 refine + streamlined output phase
// (unconditional zero-fill + sparse ones, z_q over all 256 threads).
// 1024 CTAs x 256 threads.
// ---------------------------------------------------------------------------
__global__ __launch_bounds__(256, 2) void vq_main_kernel(const float* __restrict__ z,
                                                         const float* __restrict__ emb,
                                                         float* __restrict__ out) {
    extern __shared__ float sm[];
    const uint32_t sb = smem_u32(sm);
    const int tid = threadIdx.x, lane = tid & 31, wid = tid >> 5;
    const int n0 = blockIdx.x * M_TILE;
    const int b0 = n0 >> 12, hw0 = n0 & 4095;

    float* zs  = sm + ZS_W;
    float* e2s = sm + E2_W;
    float* x2s = sm + X2_W;
    int*   bks = (int*)(sm + BK_W);
    float* ws  = sm + WS_W;

    // ---- stage z rows (coalesced) + e2, prefetch B round 0 ----
    const float* zb = z + (size_t)b0 * (DD * HWSZ) + hw0;
    #pragma unroll
    for (int i = 0; i < 32; i++) {
        int idx = tid + i * 256;
        int d = idx >> 7, p = idx & 127;
        zs[p * PITCH + d] = zb[(size_t)d * HWSZ + p];
    }
    for (int i = tid; i < KK; i += 256) e2s[i] = g_e2[i];
    stage_B(sb, B0_W, 0, tid);
    CP_COMMIT();
    __syncthreads();

    // ---- x2 per pixel (exact round-5 formula/order) ----
    if (tid < 128) {
        const float4* zr4 = (const float4*)(zs + tid * PITCH);
        float s0 = 0.f, s1 = 0.f, s2 = 0.f, s3 = 0.f;
        #pragma unroll
        for (int i = 0; i < 16; i++) {
            float4 v = zr4[i];
            s0 += v.x * v.x; s1 += v.y * v.y; s2 += v.z * v.z; s3 += v.w * v.w;
        }
        x2s[tid] = (s0 + s1) + (s2 + s3);
    }

    // ---- persistent A fragments (hi fp16 only): m16n8k16, 4 ksteps ----
    uint32_t AH[4][4];
    const int r0 = wid * 16 + (lane >> 2), r1 = r0 + 8, kq = lane & 3;
    #pragma unroll
    for (int ks = 0; ks < 4; ks++) {
        const int kbse = 16 * ks + 2 * kq;
        AH[ks][0] = pack_h2(zs[r0 * PITCH + kbse],     zs[r0 * PITCH + kbse + 1]);
        AH[ks][1] = pack_h2(zs[r1 * PITCH + kbse],     zs[r1 * PITCH + kbse + 1]);
        AH[ks][2] = pack_h2(zs[r0 * PITCH + kbse + 8], zs[r0 * PITCH + kbse + 9]);
        AH[ks][3] = pack_h2(zs[r1 * PITCH + kbse + 8], zs[r1 * PITCH + kbse + 9]);
    }

    CP_WAIT0();
    __syncthreads();               // B0 + x2s ready

    const float x2a = x2s[r0], x2b = x2s[r1];
    // MAX-metric trackers: m = c - 512*e2  (dist = x2 - m/512, monotone)
    float a1 = -3.4e38f, a2 = -3.4e38f, b1 = -3.4e38f, b2 = -3.4e38f;
    int   ai1 = 0, ai2 = 0, bi1 = 0, bi2 = 0;

    // ---- 8 rounds x 128 codes, hi-only ranking pass ----
    for (int rd = 0; rd < 8; rd++) {
        if (rd < 7) { stage_B(sb, ((rd + 1) & 1) ? B1_W : B0_W, rd + 1, tid); CP_COMMIT(); }
        const float* Bs = sm + ((rd & 1) ? B1_W : B0_W);
        const int kb = rd * 128;

        for (int pair = 0; pair < 8; pair++) {     // 2 ntiles (16 codes) per iter
            float c[2][4] = {{0.f,0.f,0.f,0.f},{0.f,0.f,0.f,0.f}};
            const int code0 = (pair * 2 + 0) * 8 + (lane >> 2);
            const int code1 = (pair * 2 + 1) * 8 + (lane >> 2);
            const uint4* q0 = (const uint4*)((const uint32_t*)Bs + code0 * PITCH_B);
            const uint4* q1 = (const uint4*)((const uint32_t*)Bs + code1 * PITCH_B);
            uint4 B0a = q0[kq * 2 + 0];   // ks 0,1 of code0's fragment column
            uint4 B0b = q0[kq * 2 + 1];   // ks 2,3
            uint4 B1a = q1[kq * 2 + 0];
            uint4 B1b = q1[kq * 2 + 1];
            mma_f16(c[0], AH[0], B0a.x, B0a.y);
            mma_f16(c[1], AH[0], B1a.x, B1a.y);
            mma_f16(c[0], AH[1], B0a.z, B0a.w);
            mma_f16(c[1], AH[1], B1a.z, B1a.w);
            mma_f16(c[0], AH[2], B0b.x, B0b.y);
            mma_f16(c[1], AH[2], B1b.x, B1b.y);
            mma_f16(c[0], AH[3], B0b.z, B0b.w);
            mma_f16(c[1], AH[3], B1b.z, B1b.w);
            #pragma unroll
            for (int t = 0; t < 2; t++) {
                const int cbase = kb + (pair * 2 + t) * 8 + 2 * kq;
                float e0 = e2s[cbase], e1 = e2s[cbase + 1];
                float m00 = fmaf(e0, -512.0f, c[t][0]);   // row r0, code cbase
                float m01 = fmaf(e1, -512.0f, c[t][1]);   // row r0, code cbase+1
                float m10 = fmaf(e0, -512.0f, c[t][2]);   // row r1
                float m11 = fmaf(e1, -512.0f, c[t][3]);
                TOP2MAX(m00, cbase,     a1, ai1, a2, ai2);
                TOP2MAX(m01, cbase + 1, a1, ai1, a2, ai2);
                TOP2MAX(m10, cbase,     b1, bi1, b2, bi2);
                TOP2MAX(m11, cbase + 1, b1, bi1, b2, bi2);
            }
        }
        if (rd < 7) { CP_WAIT0(); __syncthreads(); }
    }

    // ---- quad-merge the per-thread top2s into pixel top2 (branchless) ----
    #pragma unroll
    for (int off = 1; off <= 2; off <<= 1) {
        // row r0 tracker
        {
            float n1 = __shfl_xor_sync(0xffffffffu, a1, off);
            int   j1 = __shfl_xor_sync(0xffffffffu, ai1, off);
            float n2 = __shfl_xor_sync(0xffffffffu, a2, off);
            int   j2 = __shfl_xor_sync(0xffffffffu, ai2, off);
            bool swp = n1 > a1;
            float t1 = swp ? n1 : a1;  int ti1 = swp ? j1 : ai1;
            float alt = swp ? a1 : n1; int tai = swp ? ai1 : j1;
            float o2  = swp ? n2 : a2; int oi2 = swp ? j2 : ai2;
            bool s2p = o2 > alt;
            a1 = t1; ai1 = ti1;
            a2 = s2p ? o2 : alt; ai2 = s2p ? oi2 : tai;
        }
        // row r1 tracker
        {
            float n1 = __shfl_xor_sync(0xffffffffu, b1, off);
            int   j1 = __shfl_xor_sync(0xffffffffu, bi1, off);
            float n2 = __shfl_xor_sync(0xffffffffu, b2, off);
            int   j2 = __shfl_xor_sync(0xffffffffu, bi2, off);
            bool swp = n1 > b1;
            float t1 = swp ? n1 : b1;  int ti1 = swp ? j1 : bi1;
            float alt = swp ? b1 : n1; int tai = swp ? bi1 : j1;
            float o2  = swp ? n2 : b2; int oi2 = swp ? j2 : bi2;
            bool s2p = o2 > alt;
            b1 = t1; bi1 = ti1;
            b2 = s2p ? o2 : alt; bi2 = s2p ? oi2 : tai;
        }
    }

    // ---- exact fp32 refine: one candidate per quad lane, warp-wide loads ----
    {
        int mycode = (kq == 0) ? ai1 : (kq == 1) ? ai2 : (kq == 2) ? bi1 : bi2;
        const float* zrow = zs + ((kq < 2) ? r0 : r1) * PITCH;
        float myx2 = (kq < 2) ? x2a : x2b;
        float dex = exact_dist(zrow, myx2, mycode, emb, e2s);
        // combine candidate pairs (lanes kq^1), exact tie -> lowest index
        float dot = __shfl_xor_sync(0xffffffffu, dex, 1);
        int   cot = __shfl_xor_sync(0xffffffffu, mycode, 1);
        bool take = (dot < dex) || (dot == dex && cot < mycode);
        int kfin = take ? cot : mycode;
        if (kq == 0) bks[r0] = kfin;
        if (kq == 2) bks[r1] = kfin;
    }
    __syncthreads();   // bks ready

    // ---- output phase A: zero-fill encodings (pure store stream) + z_q ----
    const size_t enc_base = (size_t)ENC_OFF + (size_t)n0 * KK;
    {
        float4* enc4 = (float4*)(out + enc_base + 2);   // 16B aligned; 32767 valid
        const float4 zero4 = make_float4(0.f, 0.f, 0.f, 0.f);
        #pragma unroll 8
        for (int t = 0; t < 128; t++) {
            int q = t * 256 + tid;
            if (q < 32767) __stcs(&enc4[q], zero4);
        }
        if (tid == 0) { __stcs(&out[enc_base], 0.f); __stcs(&out[enc_base + 1], 0.f); }
        if (tid == 1) {
            __stcs(&out[enc_base + (size_t)127 * 1024 + 1022], 0.f);
            __stcs(&out[enc_base + (size_t)127 * 1024 + 1023], 0.f);
        }
    }

    // z_q + loss over all 256 threads: pixel p = tid&127, half hf = tid>>7
    {
        const int p  = tid & 127, hf = tid >> 7;
        const int k  = bks[p];
        const float4* erow = (const float4*)(emb + k * 64) + hf * 8;
        const float4* zr4  = (const float4*)(zs + p * PITCH) + hf * 8;
        float* o_zq = out + 1 + (size_t)b0 * (DD * HWSZ) + (size_t)hf * 32 * HWSZ
                    + ((n0 + p) & 4095);
        float sq = 0.f;
        #pragma unroll
        for (int i = 0; i < 8; i++) {
            float4 v = erow[i];
            float4 zv = zr4[i];
            __stcs(&o_zq[(size_t)(4 * i + 0) * HWSZ], v.x);
            __stcs(&o_zq[(size_t)(4 * i + 1) * HWSZ], v.y);
            __stcs(&o_zq[(size_t)(4 * i + 2) * HWSZ], v.z);
            __stcs(&o_zq[(size_t)(4 * i + 3) * HWSZ], v.w);
            float d0 = v.x - zv.x, d1 = v.y - zv.y, d2 = v.z - zv.z, d3 = v.w - zv.w;
            sq += d0 * d0 + d1 * d1 + d2 * d2 + d3 * d3;
        }
        #pragma unroll
        for (int off = 16; off; off >>= 1) sq += __shfl_down_sync(0xffffffffu, sq, off);
        if (lane == 0) ws[wid] = sq;
    }
    __syncthreads();   // zeros globally ordered before the ones; ws ready

    // ---- output phase B: sparse 1.0 writes + counts + loss ----
    if (tid < 128) {
        const int k = bks[tid];
        out[enc_base + (size_t)tid * KK + k] = 1.0f;
        atomicAdd(&g_counts[k], 1);
    }
    if (tid == 0) {
        float s = ((ws[0] + ws[1]) + (ws[2] + ws[3])) + ((ws[4] + ws[5]) + (ws[6] + ws[7]));
        atomicAdd(&g_loss, (double)s);
    }
}

// ---------------------------------------------------------------------------
// Final: vq_loss + perplexity
// ---------------------------------------------------------------------------
__global__ void final_kernel(float* __restrict__ out) {
    __shared__ float ssum[1024];
    const int k = threadIdx.x;
    float p = (float)g_counts[k] * (1.0f / (float)NPIX);
    ssum[k] = p * logf(p + 1e-10f);
    __syncthreads();
    #pragma unroll
    for (int s = 512; s; s >>= 1) {
        if (k < s) ssum[k] += ssum[k + s];
        __syncthreads();
    }
    if (k == 0) {
        out[0]         = (float)(1.25 * g_loss * (1.0 / (double)ZSIZE));
        out[1 + ZSIZE] = expf(-ssum[0]);
    }
}

// ---------------------------------------------------------------------------
extern "C" void kernel_launch(void* const* d_in, const int* in_sizes, int n_in,
                              void* d_out, int out_size) {
    const float* z   = (const float*)d_in[0];   // [32,64,64,64] f32 NCHW
    const float* emb = (const float*)d_in[1];   // [1024,64] f32
    float* out = (float*)d_out;

    cudaFuncSetAttribute(vq_main_kernel, cudaFuncAttributeMaxDynamicSharedMemorySize,
                         SMEM_BYTES);

    prep_kernel   <<<KK / 8, 256>>>(emb);
    vq_main_kernel<<<NPIX / M_TILE, 256, SMEM_BYTES>>>(z, emb, out);
    final_kernel  <<<1, 1024>>>(out);
}

// round 15
// speedup vs baseline: 1.4330x; 1.4330x over previous
#include <cuda_runtime.h>
#include <cuda_fp16.h>
#include <cstdint>

// Problem constants
#define BB     32
#define DD     64
#define HWSZ   4096
#define NPIX   131072
#define KK     1024
#define ZSIZE  8388608
#define ENC_OFF (1 + ZSIZE + 1)     // vq_loss(1), z_q, perplexity(1), encodings

#define M_TILE  128                 // pixels per CTA (256 threads, 16 px/warp)
#define PITCH   68                  // z row pitch in words
#define PITCH_B 36                  // B row pitch in words (32 half2 words + 4 pad)

// Shared memory word offsets
#define ZS_W   0                    // z rows: 128 x PITCH            (8704)
#define B0_W   8704                 // B buf0: 128 codes x PITCH_B    (4608)
#define B1_W   13312                // B buf1                         (4608)
#define E2_W   17920                // e2s[1024]
#define X2_W   18944                // x2s[128]
#define BK_W   19072                // bks[128]
#define WS_W   19200                // warp partials[8]
#define SMEM_WORDS 19208
#define SMEM_BYTES (SMEM_WORDS * 4) // 76832 B -> 2 CTAs/SM

// Scratch (device globals; no allocation allowed)
__device__ int    g_counts[KK];
__device__ double g_loss;
__device__ float  g_e2[KK];
// fp16(1024*e) packed half2 words, 32 per code (128B rows)
__device__ __align__(16) uint32_t g_embpack[KK][32];

// ---------------------------------------------------------------------------
// Helpers
// ---------------------------------------------------------------------------
__device__ __forceinline__ uint32_t smem_u32(const void* p) {
    uint32_t a;
    asm("{ .reg .u64 t; cvta.to.shared.u64 t, %1; cvt.u32.u64 %0, t; }" : "=r"(a) : "l"(p));
    return a;
}
__device__ __forceinline__ uint32_t pack_h2(float a, float b) {
    __half2 h = __halves2half2(__float2half_rn(a), __float2half_rn(b));
    return *(uint32_t*)&h;
}
__device__ __forceinline__ void mma_f16(float c[4], const uint32_t a[4],
                                        uint32_t b0, uint32_t b1) {
    asm volatile("mma.sync.aligned.m16n8k16.row.col.f32.f16.f16.f32 "
                 "{%0,%1,%2,%3}, {%4,%5,%6,%7}, {%8,%9}, {%0,%1,%2,%3};"
                 : "+f"(c[0]), "+f"(c[1]), "+f"(c[2]), "+f"(c[3])
                 : "r"(a[0]), "r"(a[1]), "r"(a[2]), "r"(a[3]), "r"(b0), "r"(b1));
}
__device__ __forceinline__ void cp16(uint32_t dst, const void* src) {
    asm volatile("cp.async.cg.shared.global [%0], [%1], 16;" :: "r"(dst), "l"(src));
}
#define CP_COMMIT() asm volatile("cp.async.commit_group;" ::: "memory")
#define CP_WAIT0()  asm volatile("cp.async.wait_group 0;" ::: "memory")

// Branchless MAX-top2 update (strict >: earlier/lower index kept on ties).
#define TOP2MAX(m, k, m1, i1, m2, i2) do {                 \
    bool g1 = (m) > (m1);                                  \
    bool g2 = (m) > (m2);                                  \
    float _nm2 = g1 ? (m1) : (g2 ? (m) : (m2));            \
    int   _ni2 = g1 ? (i1) : (g2 ? (k) : (i2));            \
    (m1) = g1 ? (m) : (m1);                                \
    (i1) = g1 ? (k) : (i1);                                \
    (m2) = _nm2; (i2) = _ni2;                              \
} while (0)

// Exact fp32 distance, replicating round-5's verified formula/order exactly.
__device__ __forceinline__ float exact_dist(const float* zrow, float x2, int k,
                                            const float* __restrict__ emb,
                                            const float* e2s) {
    const float4* e4 = (const float4*)(emb + k * 64);
    const float4* z4 = (const float4*)zrow;
    float s0 = 0.f, s1 = 0.f, s2 = 0.f, s3 = 0.f;
    #pragma unroll
    for (int i = 0; i < 16; i++) {
        float4 e = e4[i], zv = z4[i];
        s0 += zv.x * e.x; s1 += zv.y * e.y; s2 += zv.z * e.z; s3 += zv.w * e.w;
    }
    float ip = (s0 + s1) + (s2 + s3);
    return (x2 + e2s[k]) - 2.0f * ip;
}

// Stage one 128-code round: 128 rows x 128B at pitch 144B.
__device__ __forceinline__ void stage_B(uint32_t sb, int bufw, int round, int tid) {
    const char* src = (const char*)&g_embpack[round * 128][0];
    #pragma unroll
    for (int t = 0; t < 4; t++) {
        int idx = tid + t * 256;
        int row = idx >> 3, j = idx & 7;            // 8 x 16B = 128B per row
        uint32_t dst = sb + (uint32_t)(bufw + row * PITCH_B) * 4 + j * 16;
        cp16(dst, src + row * 128 + j * 16);
    }
}

// ---------------------------------------------------------------------------
// Prep: one code per warp. e2 (warp-reduced), fp16(1024*e) hi pack,
// zero scratch. Grid 128 x 256.
// ---------------------------------------------------------------------------
__global__ void prep_kernel(const float* __restrict__ emb) {
    const int code = blockIdx.x * 8 + (threadIdx.x >> 5);
    const int lane = threadIdx.x & 31;
    float2 v = ((const float2*)(emb + code * 64))[lane];

    float sq = v.x * v.x + v.y * v.y;
    #pragma unroll
    for (int off = 16; off; off >>= 1) sq += __shfl_xor_sync(0xffffffffu, sq, off);
    if (lane == 0) g_e2[code] = sq;

    g_embpack[code][lane] = pack_h2(v.x * 1024.0f, v.y * 1024.0f);

    int gid = blockIdx.x * 256 + threadIdx.x;
    if (gid < KK) g_counts[gid] = 0;
    if (gid == 0) g_loss = 0.0;
}

// ---------------------------------------------------------------------------
// Main fused kernel: hi-only fp16 mma ranking (branchless top-2 in c-space)
// + quad-merge + 1-code-per-lane exact fp32 refine + z_q + loss + counts +
// one-hot encodings (zero-fill + sparse ones). 1024 CTAs x 256 threads.
// ---------------------------------------------------------------------------
__global__ __launch_bounds__(256, 2) void vq_main_kernel(const float* __restrict__ z,
                                                         const float* __restrict__ emb,
                                                         float* __restrict__ out) {
    extern __shared__ float sm[];
    const uint32_t sb = smem_u32(sm);
    const int tid = threadIdx.x, lane = tid & 31, wid = tid >> 5;
    const int n0 = blockIdx.x * M_TILE;
    const int b0 = n0 >> 12, hw0 = n0 & 4095;

    float* zs  = sm + ZS_W;
    float* e2s = sm + E2_W;
    float* x2s = sm + X2_W;
    int*   bks = (int*)(sm + BK_W);
    float* ws  = sm + WS_W;

    // ---- stage z rows (coalesced) + e2, prefetch B round 0 ----
    const float* zb = z + (size_t)b0 * (DD * HWSZ) + hw0;
    #pragma unroll
    for (int i = 0; i < 32; i++) {
        int idx = tid + i * 256;
        int d = idx >> 7, p = idx & 127;
        zs[p * PITCH + d] = zb[(size_t)d * HWSZ + p];
    }
    for (int i = tid; i < KK; i += 256) e2s[i] = g_e2[i];
    stage_B(sb, B0_W, 0, tid);
    CP_COMMIT();
    __syncthreads();

    // ---- x2 per pixel (exact round-5 formula/order) ----
    if (tid < 128) {
        const float4* zr4 = (const float4*)(zs + tid * PITCH);
        float s0 = 0.f, s1 = 0.f, s2 = 0.f, s3 = 0.f;
        #pragma unroll
        for (int i = 0; i < 16; i++) {
            float4 v = zr4[i];
            s0 += v.x * v.x; s1 += v.y * v.y; s2 += v.z * v.z; s3 += v.w * v.w;
        }
        x2s[tid] = (s0 + s1) + (s2 + s3);
    }

    // ---- persistent A fragments (hi fp16 only): m16n8k16, 4 ksteps ----
    uint32_t AH[4][4];
    const int r0 = wid * 16 + (lane >> 2), r1 = r0 + 8, kq = lane & 3;
    #pragma unroll
    for (int ks = 0; ks < 4; ks++) {
        const int kbse = 16 * ks + 2 * kq;
        AH[ks][0] = pack_h2(zs[r0 * PITCH + kbse],     zs[r0 * PITCH + kbse + 1]);
        AH[ks][1] = pack_h2(zs[r1 * PITCH + kbse],     zs[r1 * PITCH + kbse + 1]);
        AH[ks][2] = pack_h2(zs[r0 * PITCH + kbse + 8], zs[r0 * PITCH + kbse + 9]);
        AH[ks][3] = pack_h2(zs[r1 * PITCH + kbse + 8], zs[r1 * PITCH + kbse + 9]);
    }

    CP_WAIT0();
    __syncthreads();               // B0 + x2s ready

    const float x2a = x2s[r0], x2b = x2s[r1];
    // MAX-metric trackers: m = c - 512*e2  (dist = x2 - m/512, monotone)
    float a1 = -3.4e38f, a2 = -3.4e38f, b1 = -3.4e38f, b2 = -3.4e38f;
    int   ai1 = 0, ai2 = 0, bi1 = 0, bi2 = 0;

    // ---- 8 rounds x 128 codes, hi-only ranking pass ----
    for (int rd = 0; rd < 8; rd++) {
        if (rd < 7) { stage_B(sb, ((rd + 1) & 1) ? B1_W : B0_W, rd + 1, tid); CP_COMMIT(); }
        const float* Bs = sm + ((rd & 1) ? B1_W : B0_W);
        const int kb = rd * 128;

        for (int pair = 0; pair < 8; pair++) {     // 2 ntiles (16 codes) per iter
            float c[2][4] = {{0.f,0.f,0.f,0.f},{0.f,0.f,0.f,0.f}};
            const int code0 = (pair * 2 + 0) * 8 + (lane >> 2);
            const int code1 = (pair * 2 + 1) * 8 + (lane >> 2);
            const uint32_t* q0 = (const uint32_t*)Bs + code0 * PITCH_B;
            const uint32_t* q1 = (const uint32_t*)Bs + code1 * PITCH_B;
            #pragma unroll
            for (int ks = 0; ks < 4; ks++) {
                const int j = 8 * ks + kq;
                mma_f16(c[0], AH[ks], q0[j], q0[j + 4]);
                mma_f16(c[1], AH[ks], q1[j], q1[j + 4]);
            }
            #pragma unroll
            for (int t = 0; t < 2; t++) {
                const int cbase = kb + (pair * 2 + t) * 8 + 2 * kq;
                float e0 = e2s[cbase], e1 = e2s[cbase + 1];
                float m00 = fmaf(e0, -512.0f, c[t][0]);   // row r0, code cbase
                float m01 = fmaf(e1, -512.0f, c[t][1]);   // row r0, code cbase+1
                float m10 = fmaf(e0, -512.0f, c[t][2]);   // row r1
                float m11 = fmaf(e1, -512.0f, c[t][3]);
                TOP2MAX(m00, cbase,     a1, ai1, a2, ai2);
                TOP2MAX(m01, cbase + 1, a1, ai1, a2, ai2);
                TOP2MAX(m10, cbase,     b1, bi1, b2, bi2);
                TOP2MAX(m11, cbase + 1, b1, bi1, b2, bi2);
            }
        }
        if (rd < 7) { CP_WAIT0(); __syncthreads(); }
    }

    // ---- quad-merge the per-thread top2s into pixel top2 (branchless) ----
    #pragma unroll
    for (int off = 1; off <= 2; off <<= 1) {
        // row r0 tracker
        {
            float n1 = __shfl_xor_sync(0xffffffffu, a1, off);
            int   j1 = __shfl_xor_sync(0xffffffffu, ai1, off);
            float n2 = __shfl_xor_sync(0xffffffffu, a2, off);
            int   j2 = __shfl_xor_sync(0xffffffffu, ai2, off);
            bool swp = n1 > a1;
            float t1 = swp ? n1 : a1;  int ti1 = swp ? j1 : ai1;
            float alt = swp ? a1 : n1; int tai = swp ? ai1 : j1;
            float o2  = swp ? n2 : a2; int oi2 = swp ? j2 : ai2;
            bool s2p = o2 > alt;
            a1 = t1; ai1 = ti1;
            a2 = s2p ? o2 : alt; ai2 = s2p ? oi2 : tai;
        }
        // row r1 tracker
        {
            float n1 = __shfl_xor_sync(0xffffffffu, b1, off);
            int   j1 = __shfl_xor_sync(0xffffffffu, bi1, off);
            float n2 = __shfl_xor_sync(0xffffffffu, b2, off);
            int   j2 = __shfl_xor_sync(0xffffffffu, bi2, off);
            bool swp = n1 > b1;
            float t1 = swp ? n1 : b1;  int ti1 = swp ? j1 : bi1;
            float alt = swp ? b1 : n1; int tai = swp ? bi1 : j1;
            float o2  = swp ? n2 : b2; int oi2 = swp ? j2 : bi2;
            bool s2p = o2 > alt;
            b1 = t1; bi1 = ti1;
            b2 = s2p ? o2 : alt; bi2 = s2p ? oi2 : tai;
        }
    }

    // ---- exact fp32 refine: one candidate per quad lane, warp-wide loads ----
    {
        int mycode = (kq == 0) ? ai1 : (kq == 1) ? ai2 : (kq == 2) ? bi1 : bi2;
        const float* zrow = zs + ((kq < 2) ? r0 : r1) * PITCH;
        float myx2 = (kq < 2) ? x2a : x2b;
        float dex = exact_dist(zrow, myx2, mycode, emb, e2s);
        // combine candidate pairs (lanes kq^1), exact tie -> lowest index
        float dot = __shfl_xor_sync(0xffffffffu, dex, 1);
        int   cot = __shfl_xor_sync(0xffffffffu, mycode, 1);
        bool take = (dot < dex) || (dot == dex && cot < mycode);
        int kfin = take ? cot : mycode;
        if (kq == 0) bks[r0] = kfin;
        if (kq == 2) bks[r1] = kfin;
    }
    __syncthreads();

    // ---- outputs: z_q gather + loss (R11-identical), then encodings ----
    if (tid < 128) {
        const int n  = n0 + tid;
        const int k  = bks[tid];
        atomicAdd(&g_counts[k], 1);

        const float4* erow = (const float4*)(emb + k * 64);
        const float4* zr4  = (const float4*)(zs + tid * PITCH);
        float* o_zq = out + 1 + (size_t)b0 * (DD * HWSZ) + (n & 4095);
        float sq = 0.f;
        #pragma unroll
        for (int i = 0; i < 16; i++) {
            float4 v = erow[i];
            float4 zv = zr4[i];
            o_zq[(size_t)(4 * i + 0) * HWSZ] = v.x;
            o_zq[(size_t)(4 * i + 1) * HWSZ] = v.y;
            o_zq[(size_t)(4 * i + 2) * HWSZ] = v.z;
            o_zq[(size_t)(4 * i + 3) * HWSZ] = v.w;
            float d0 = v.x - zv.x, d1 = v.y - zv.y, d2 = v.z - zv.z, d3 = v.w - zv.w;
            sq += d0 * d0 + d1 * d1 + d2 * d2 + d3 * d3;
        }
        #pragma unroll
        for (int off = 16; off; off >>= 1) sq += __shfl_down_sync(0xffffffffu, sq, off);
        if (lane == 0) ws[wid] = sq;
    }
    __syncthreads();
    if (tid == 0) atomicAdd(&g_loss, (double)((ws[0] + ws[1]) + (ws[2] + ws[3])));

    // One-hot encodings: unconditional zero-fill (pure STG.128 stream), then
    // sparse 1.0 writes. Intra-CTA ordering via __syncthreads (R12-validated);
    // each CTA owns its 512KB slab exclusively.
    {
        const size_t enc_base = (size_t)ENC_OFF + (size_t)n0 * KK;
        float4* enc4 = (float4*)(out + enc_base + 2);   // 16B aligned; 32767 valid
        const float4 zero4 = make_float4(0.f, 0.f, 0.f, 0.f);
        #pragma unroll 8
        for (int t = 0; t < 128; t++) {
            int q = t * 256 + tid;
            if (q < 32767) enc4[q] = zero4;
        }
        if (tid == 0) { out[enc_base] = 0.f; out[enc_base + 1] = 0.f; }
        if (tid == 1) {
            out[enc_base + (size_t)127 * 1024 + 1022] = 0.f;
            out[enc_base + (size_t)127 * 1024 + 1023] = 0.f;
        }
        __syncthreads();   // zeros complete (intra-CTA order) before the ones
        if (tid < 128) {
            out[enc_base + (size_t)tid * KK + bks[tid]] = 1.0f;
        }
    }
}

// ---------------------------------------------------------------------------
// Final: vq_loss + perplexity
// ---------------------------------------------------------------------------
__global__ void final_kernel(float* __restrict__ out) {
    __shared__ float ssum[1024];
    const int k = threadIdx.x;
    float p = (float)g_counts[k] * (1.0f / (float)NPIX);
    ssum[k] = p * logf(p + 1e-10f);
    __syncthreads();
    #pragma unroll
    for (int s = 512; s; s >>= 1) {
        if (k < s) ssum[k] += ssum[k + s];
        __syncthreads();
    }
    if (k == 0) {
        out[0]         = (float)(1.25 * g_loss * (1.0 / (double)ZSIZE));
        out[1 + ZSIZE] = expf(-ssum[0]);
    }
}

// ---------------------------------------------------------------------------
extern "C" void kernel_launch(void* const* d_in, const int* in_sizes, int n_in,
                              void* d_out, int out_size) {
    const float* z   = (const float*)d_in[0];   // [32,64,64,64] f32 NCHW
    const float* emb = (const float*)d_in[1];   // [1024,64] f32
    float* out = (float*)d_out;

    cudaFuncSetAttribute(vq_main_kernel, cudaFuncAttributeMaxDynamicSharedMemorySize,
                         SMEM_BYTES);

    prep_kernel   <<<KK / 8, 256>>>(emb);
    vq_main_kernel<<<NPIX / M_TILE, 256, SMEM_BYTES>>>(z, emb, out);
    final_kernel  <<<1, 1024>>>(out);
}

// round 17
// speedup vs baseline: 1.5759x; 1.0997x over previous
#include <cuda_runtime.h>
#include <cuda_fp16.h>
#include <cstdint>

// Problem constants
#define BB     32
#define DD     64
#define HWSZ   4096
#define NPIX   131072
#define KK     1024
#define ZSIZE  8388608
#define ENC_OFF (1 + ZSIZE + 1)     // vq_loss(1), z_q, perplexity(1), encodings

#define M_TILE  128                 // pixels per CTA (256 threads, 16 px/warp)
#define PITCH   68                  // z row pitch in words
#define PITCH_B 36                  // B row pitch in words (32 half2 words + 4 pad)

// Shared memory word offsets
#define ZS_W   0                    // z rows: 128 x PITCH            (8704)
#define B0_W   8704                 // B buf0: 128 codes x PITCH_B    (4608)
#define B1_W   13312                // B buf1                         (4608)
#define E2_W   17920                // e2s[1024]
#define X2_W   18944                // x2s[128]
#define BK_W   19072                // bks[128]
#define WS_W   19200                // warp partials[8]
#define SMEM_WORDS 19208
#define SMEM_BYTES (SMEM_WORDS * 4) // 76832 B -> 2 CTAs/SM

// Scratch (device globals; no allocation allowed)
__device__ int    g_counts[KK];
__device__ double g_loss;
__device__ float  g_e2[KK];
// fp16(1024*e) packed half2 words, 32 per code (128B rows)
__device__ __align__(16) uint32_t g_embpack[KK][32];

// ---------------------------------------------------------------------------
// Helpers
// ---------------------------------------------------------------------------
__device__ __forceinline__ uint32_t smem_u32(const void* p) {
    uint32_t a;
    asm("{ .reg .u64 t; cvta.to.shared.u64 t, %1; cvt.u32.u64 %0, t; }" : "=r"(a) : "l"(p));
    return a;
}
__device__ __forceinline__ uint32_t pack_h2(float a, float b) {
    __half2 h = __halves2half2(__float2half_rn(a), __float2half_rn(b));
    return *(uint32_t*)&h;
}
__device__ __forceinline__ void mma_f16(float c[4], const uint32_t a[4],
                                        uint32_t b0, uint32_t b1) {
    asm volatile("mma.sync.aligned.m16n8k16.row.col.f32.f16.f16.f32 "
                 "{%0,%1,%2,%3}, {%4,%5,%6,%7}, {%8,%9}, {%0,%1,%2,%3};"
                 : "+f"(c[0]), "+f"(c[1]), "+f"(c[2]), "+f"(c[3])
                 : "r"(a[0]), "r"(a[1]), "r"(a[2]), "r"(a[3]), "r"(b0), "r"(b1));
}
__device__ __forceinline__ void cp16(uint32_t dst, const void* src) {
    asm volatile("cp.async.cg.shared.global [%0], [%1], 16;" :: "r"(dst), "l"(src));
}
#define CP_COMMIT() asm volatile("cp.async.commit_group;" ::: "memory")
#define CP_WAIT0()  asm volatile("cp.async.wait_group 0;" ::: "memory")

// Branchless MAX-top2 update (strict >: earlier/lower index kept on ties).
#define TOP2MAX(m, k, m1, i1, m2, i2) do {                 \
    bool g1 = (m) > (m1);                                  \
    bool g2 = (m) > (m2);                                  \
    float _nm2 = g1 ? (m1) : (g2 ? (m) : (m2));            \
    int   _ni2 = g1 ? (i1) : (g2 ? (k) : (i2));            \
    (m1) = g1 ? (m) : (m1);                                \
    (i1) = g1 ? (k) : (i1);                                \
    (m2) = _nm2; (i2) = _ni2;                              \
} while (0)

// Exact fp32 distance, replicating round-5's verified formula/order exactly.
__device__ __forceinline__ float exact_dist(const float* zrow, float x2, int k,
                                            const float* __restrict__ emb,
                                            const float* e2s) {
    const float4* e4 = (const float4*)(emb + k * 64);
    const float4* z4 = (const float4*)zrow;
    float s0 = 0.f, s1 = 0.f, s2 = 0.f, s3 = 0.f;
    #pragma unroll
    for (int i = 0; i < 16; i++) {
        float4 e = e4[i], zv = z4[i];
        s0 += zv.x * e.x; s1 += zv.y * e.y; s2 += zv.z * e.z; s3 += zv.w * e.w;
    }
    float ip = (s0 + s1) + (s2 + s3);
    return (x2 + e2s[k]) - 2.0f * ip;
}

// Stage one 128-code round: 128 rows x 128B at pitch 144B.
__device__ __forceinline__ void stage_B(uint32_t sb, int bufw, int round, int tid) {
    const char* src = (const char*)&g_embpack[round * 128][0];
    #pragma unroll
    for (int t = 0; t < 4; t++) {
        int idx = tid + t * 256;
        int row = idx >> 3, j = idx & 7;            // 8 x 16B = 128B per row
        uint32_t dst = sb + (uint32_t)(bufw + row * PITCH_B) * 4 + j * 16;
        cp16(dst, src + row * 128 + j * 16);
    }
}

// ---------------------------------------------------------------------------
// Prep: one code per warp. e2 (warp-reduced), fp16(1024*e) hi pack,
// zero scratch. Grid 128 x 256.
// ---------------------------------------------------------------------------
__global__ void prep_kernel(const float* __restrict__ emb) {
    const int code = blockIdx.x * 8 + (threadIdx.x >> 5);
    const int lane = threadIdx.x & 31;
    float2 v = ((const float2*)(emb + code * 64))[lane];

    float sq = v.x * v.x + v.y * v.y;
    #pragma unroll
    for (int off = 16; off; off >>= 1) sq += __shfl_xor_sync(0xffffffffu, sq, off);
    if (lane == 0) g_e2[code] = sq;

    g_embpack[code][lane] = pack_h2(v.x * 1024.0f, v.y * 1024.0f);

    int gid = blockIdx.x * 256 + threadIdx.x;
    if (gid < KK) g_counts[gid] = 0;
    if (gid == 0) g_loss = 0.0;
}

// ---------------------------------------------------------------------------
// Main fused kernel: hi-only fp16 mma ranking (branchless top-2 in c-space)
// + quad-merge + 1-code-per-lane exact fp32 refine + z_q + loss + counts +
// one-hot encodings. 1024 CTAs x 256 threads.
// ---------------------------------------------------------------------------
__global__ __launch_bounds__(256, 2) void vq_main_kernel(const float* __restrict__ z,
                                                         const float* __restrict__ emb,
                                                         float* __restrict__ out) {
    extern __shared__ float sm[];
    const uint32_t sb = smem_u32(sm);
    const int tid = threadIdx.x, lane = tid & 31, wid = tid >> 5;
    const int n0 = blockIdx.x * M_TILE;
    const int b0 = n0 >> 12, hw0 = n0 & 4095;

    float* zs  = sm + ZS_W;
    float* e2s = sm + E2_W;
    float* x2s = sm + X2_W;
    int*   bks = (int*)(sm + BK_W);
    float* ws  = sm + WS_W;

    // ---- stage z rows (coalesced) + e2, prefetch B round 0 ----
    const float* zb = z + (size_t)b0 * (DD * HWSZ) + hw0;
    #pragma unroll
    for (int i = 0; i < 32; i++) {
        int idx = tid + i * 256;
        int d = idx >> 7, p = idx & 127;
        zs[p * PITCH + d] = zb[(size_t)d * HWSZ + p];
    }
    for (int i = tid; i < KK; i += 256) e2s[i] = g_e2[i];
    stage_B(sb, B0_W, 0, tid);
    CP_COMMIT();
    __syncthreads();

    // ---- x2 per pixel (exact round-5 formula/order) ----
    if (tid < 128) {
        const float4* zr4 = (const float4*)(zs + tid * PITCH);
        float s0 = 0.f, s1 = 0.f, s2 = 0.f, s3 = 0.f;
        #pragma unroll
        for (int i = 0; i < 16; i++) {
            float4 v = zr4[i];
            s0 += v.x * v.x; s1 += v.y * v.y; s2 += v.z * v.z; s3 += v.w * v.w;
        }
        x2s[tid] = (s0 + s1) + (s2 + s3);
    }

    // ---- persistent A fragments (hi fp16 only): m16n8k16, 4 ksteps ----
    uint32_t AH[4][4];
    const int r0 = wid * 16 + (lane >> 2), r1 = r0 + 8, kq = lane & 3;
    #pragma unroll
    for (int ks = 0; ks < 4; ks++) {
        const int kbse = 16 * ks + 2 * kq;
        AH[ks][0] = pack_h2(zs[r0 * PITCH + kbse],     zs[r0 * PITCH + kbse + 1]);
        AH[ks][1] = pack_h2(zs[r1 * PITCH + kbse],     zs[r1 * PITCH + kbse + 1]);
        AH[ks][2] = pack_h2(zs[r0 * PITCH + kbse + 8], zs[r0 * PITCH + kbse + 9]);
        AH[ks][3] = pack_h2(zs[r1 * PITCH + kbse + 8], zs[r1 * PITCH + kbse + 9]);
    }

    CP_WAIT0();
    __syncthreads();               // B0 + x2s ready

    const float x2a = x2s[r0], x2b = x2s[r1];
    // MAX-metric trackers: m = c - 512*e2  (dist = x2 - m/512, monotone)
    float a1 = -3.4e38f, a2 = -3.4e38f, b1 = -3.4e38f, b2 = -3.4e38f;
    int   ai1 = 0, ai2 = 0, bi1 = 0, bi2 = 0;

    // ---- 8 rounds x 128 codes, hi-only ranking pass ----
    for (int rd = 0; rd < 8; rd++) {
        if (rd < 7) { stage_B(sb, ((rd + 1) & 1) ? B1_W : B0_W, rd + 1, tid); CP_COMMIT(); }
        const float* Bs = sm + ((rd & 1) ? B1_W : B0_W);
        const int kb = rd * 128;

        for (int pair = 0; pair < 8; pair++) {     // 2 ntiles (16 codes) per iter
            float c[2][4] = {{0.f,0.f,0.f,0.f},{0.f,0.f,0.f,0.f}};
            const int code0 = (pair * 2 + 0) * 8 + (lane >> 2);
            const int code1 = (pair * 2 + 1) * 8 + (lane >> 2);
            const uint32_t* q0 = (const uint32_t*)Bs + code0 * PITCH_B;
            const uint32_t* q1 = (const uint32_t*)Bs + code1 * PITCH_B;
            #pragma unroll
            for (int ks = 0; ks < 4; ks++) {
                const int j = 8 * ks + kq;
                mma_f16(c[0], AH[ks], q0[j], q0[j + 4]);
                mma_f16(c[1], AH[ks], q1[j], q1[j + 4]);
            }
            #pragma unroll
            for (int t = 0; t < 2; t++) {
                const int cbase = kb + (pair * 2 + t) * 8 + 2 * kq;
                float e0 = e2s[cbase], e1 = e2s[cbase + 1];
                float m00 = fmaf(e0, -512.0f, c[t][0]);   // row r0, code cbase
                float m01 = fmaf(e1, -512.0f, c[t][1]);   // row r0, code cbase+1
                float m10 = fmaf(e0, -512.0f, c[t][2]);   // row r1
                float m11 = fmaf(e1, -512.0f, c[t][3]);
                TOP2MAX(m00, cbase,     a1, ai1, a2, ai2);
                TOP2MAX(m01, cbase + 1, a1, ai1, a2, ai2);
                TOP2MAX(m10, cbase,     b1, bi1, b2, bi2);
                TOP2MAX(m11, cbase + 1, b1, bi1, b2, bi2);
            }
        }
        if (rd < 7) { CP_WAIT0(); __syncthreads(); }
    }

    // ---- quad-merge the per-thread top2s into pixel top2 (branchless) ----
    #pragma unroll
    for (int off = 1; off <= 2; off <<= 1) {
        // row r0 tracker
        {
            float n1 = __shfl_xor_sync(0xffffffffu, a1, off);
            int   j1 = __shfl_xor_sync(0xffffffffu, ai1, off);
            float n2 = __shfl_xor_sync(0xffffffffu, a2, off);
            int   j2 = __shfl_xor_sync(0xffffffffu, ai2, off);
            bool swp = n1 > a1;
            float t1 = swp ? n1 : a1;  int ti1 = swp ? j1 : ai1;
            float alt = swp ? a1 : n1; int tai = swp ? ai1 : j1;
            float o2  = swp ? n2 : a2; int oi2 = swp ? j2 : ai2;
            bool s2p = o2 > alt;
            a1 = t1; ai1 = ti1;
            a2 = s2p ? o2 : alt; ai2 = s2p ? oi2 : tai;
        }
        // row r1 tracker
        {
            float n1 = __shfl_xor_sync(0xffffffffu, b1, off);
            int   j1 = __shfl_xor_sync(0xffffffffu, bi1, off);
            float n2 = __shfl_xor_sync(0xffffffffu, b2, off);
            int   j2 = __shfl_xor_sync(0xffffffffu, bi2, off);
            bool swp = n1 > b1;
            float t1 = swp ? n1 : b1;  int ti1 = swp ? j1 : bi1;
            float alt = swp ? b1 : n1; int tai = swp ? bi1 : j1;
            float o2  = swp ? n2 : b2; int oi2 = swp ? j2 : bi2;
            bool s2p = o2 > alt;
            b1 = t1; bi1 = ti1;
            b2 = s2p ? o2 : alt; bi2 = s2p ? oi2 : tai;
        }
    }

    // ---- exact fp32 refine: one candidate per quad lane, warp-wide loads ----
    {
        int mycode = (kq == 0) ? ai1 : (kq == 1) ? ai2 : (kq == 2) ? bi1 : bi2;
        const float* zrow = zs + ((kq < 2) ? r0 : r1) * PITCH;
        float myx2 = (kq < 2) ? x2a : x2b;
        float dex = exact_dist(zrow, myx2, mycode, emb, e2s);
        // combine candidate pairs (lanes kq^1), exact tie -> lowest index
        float dot = __shfl_xor_sync(0xffffffffu, dex, 1);
        int   cot = __shfl_xor_sync(0xffffffffu, mycode, 1);
        bool take = (dot < dex) || (dot == dex && cot < mycode);
        int kfin = take ? cot : mycode;
        if (kq == 0) bks[r0] = kfin;
        if (kq == 2) bks[r1] = kfin;
    }
    __syncthreads();

    // ---- outputs (validated round-5/8/9/11 logic) ----
    if (tid < 128) {
        const int n  = n0 + tid;
        const int k  = bks[tid];
        atomicAdd(&g_counts[k], 1);

        const float4* erow = (const float4*)(emb + k * 64);
        const float4* zr4  = (const float4*)(zs + tid * PITCH);
        float* o_zq = out + 1 + (size_t)b0 * (DD * HWSZ) + (n & 4095);
        float sq = 0.f;
        #pragma unroll
        for (int i = 0; i < 16; i++) {
            float4 v = erow[i];
            float4 zv = zr4[i];
            o_zq[(size_t)(4 * i + 0) * HWSZ] = v.x;
            o_zq[(size_t)(4 * i + 1) * HWSZ] = v.y;
            o_zq[(size_t)(4 * i + 2) * HWSZ] = v.z;
            o_zq[(size_t)(4 * i + 3) * HWSZ] = v.w;
            float d0 = v.x - zv.x, d1 = v.y - zv.y, d2 = v.z - zv.z, d3 = v.w - zv.w;
            sq += d0 * d0 + d1 * d1 + d2 * d2 + d3 * d3;
        }
        #pragma unroll
        for (int off = 16; off; off >>= 1) sq += __shfl_down_sync(0xffffffffu, sq, off);
        if (lane == 0) ws[wid] = sq;
    }
    __syncthreads();
    if (tid == 0) atomicAdd(&g_loss, (double)((ws[0] + ws[1]) + (ws[2] + ws[3])));

    // One-hot encodings: 512KB per CTA, STG.128 aligned body.
    {
        const size_t base = (size_t)ENC_OFF + (size_t)n0 * KK;
        if (tid == 0) {
            int kk0 = bks[0];
            out[base + 0] = (kk0 == 0) ? 1.f : 0.f;
            out[base + 1] = (kk0 == 1) ? 1.f : 0.f;
        }
        if (tid == 1) {
            int kl = bks[127];
            out[base + (size_t)127 * 1024 + 1022] = (kl == 1022) ? 1.f : 0.f;
            out[base + (size_t)127 * 1024 + 1023] = (kl == 1023) ? 1.f : 0.f;
        }
        float4* enc4 = (float4*)(out + base + 2);   // 16B aligned
        for (int q = tid; q < 32767; q += 256) {
            int p = 2 + 4 * q;
            int row = p >> 10, col = p & 1023;
            int k0 = bks[row];
            float4 v;
            if (col <= 1020) {
                v.x = (col     == k0) ? 1.f : 0.f;
                v.y = (col + 1 == k0) ? 1.f : 0.f;
                v.z = (col + 2 == k0) ? 1.f : 0.f;
                v.w = (col + 3 == k0) ? 1.f : 0.f;
            } else {  // col == 1022 spans rows row / row+1
                int k1 = bks[row + 1];
                v.x = (1022 == k0) ? 1.f : 0.f;
                v.y = (1023 == k0) ? 1.f : 0.f;
                v.z = (0 == k1) ? 1.f : 0.f;
                v.w = (1 == k1) ? 1.f : 0.f;
            }
            enc4[q] = v;
        }
    }
}

// ---------------------------------------------------------------------------
// Final: vq_loss + perplexity
// ---------------------------------------------------------------------------
__global__ void final_kernel(float* __restrict__ out) {
    __shared__ float ssum[1024];
    const int k = threadIdx.x;
    float p = (float)g_counts[k] * (1.0f / (float)NPIX);
    ssum[k] = p * logf(p + 1e-10f);
    __syncthreads();
    #pragma unroll
    for (int s = 512; s; s >>= 1) {
        if (k < s) ssum[k] += ssum[k + s];
        __syncthreads();
    }
    if (k == 0) {
        out[0]         = (float)(1.25 * g_loss * (1.0 / (double)ZSIZE));
        out[1 + ZSIZE] = expf(-ssum[0]);
    }
}

// ---------------------------------------------------------------------------
extern "C" void kernel_launch(void* const* d_in, const int* in_sizes, int n_in,
                              void* d_out, int out_size) {
    const float* z   = (const float*)d_in[0];   // [32,64,64,64] f32 NCHW
    const float* emb = (const float*)d_in[1];   // [1024,64] f32
    float* out = (float*)d_out;

    cudaFuncSetAttribute(vq_main_kernel, cudaFuncAttributeMaxDynamicSharedMemorySize,
                         SMEM_BYTES);

    prep_kernel   <<<KK / 8, 256>>>(emb);
    vq_main_kernel<<<NPIX / M_TILE, 256, SMEM_BYTES>>>(z, emb, out);
    final_kernel  <<<1, 1024>>>(out);
}